// round 13
// baseline (speedup 1.0000x reference)
#include <cuda_runtime.h>
#include <cuda_bf16.h>
#include <cstdint>
#include <math.h>

#define S   2048
#define H   2048
#define ROOM 256
#define NH  16
#define HD  128
#define SCALE 0.08838834764831845f  // 1/sqrt(128)

typedef __nv_bfloat16 bf16;

// ---------------- device globals (allocation-free scratch) ----------------
__device__ __align__(16) bf16 g_Hh [(size_t)S*H],    g_Hl [(size_t)S*H];     // hidden planes
__device__ __align__(16) bf16 g_QBh[(size_t)H*H],    g_QBl[(size_t)H*H];     // q_block planes
__device__ __align__(16) bf16 g_KBh[(size_t)ROOM*H], g_KBl[(size_t)ROOM*H];  // k_block planes
__device__ __align__(16) bf16 g_VBh[(size_t)ROOM*H], g_VBl[(size_t)ROOM*H];  // v_block planes
__device__ __align__(16) bf16 g_OBth[(size_t)H*H],   g_OBtl[(size_t)H*H];    // o_active^T [n][t]
__device__ __align__(16) bf16 g_Qh [(size_t)S*H],    g_Ql [(size_t)S*H];     // Q projection planes
__device__ __align__(16) bf16 g_Kh [(size_t)S*ROOM], g_Kl [(size_t)S*ROOM];  // k_one planes
__device__ __align__(16) bf16 g_Vth[(size_t)ROOM*S], g_Vtl[(size_t)ROOM*S];  // v_one^T [d][s]
__device__ __align__(16) bf16 g_Ah [(size_t)S*H],    g_Al [(size_t)S*H];     // attn_out planes
__device__ int g_rooms[8];

// ---------------- helpers ----------------
__device__ __forceinline__ uint32_t smem_u32(const void* p) {
    uint32_t a;
    asm("{ .reg .u64 t; cvta.to.shared.u64 t, %1; cvt.u32.u64 %0, t; }" : "=r"(a) : "l"(p));
    return a;
}
__device__ __forceinline__ void split1(float x, bf16& h, bf16& l) {
    h = __float2bfloat16_rn(x);
    l = __float2bfloat16_rn(x - __bfloat162float(h));
}
__device__ __forceinline__ unsigned pack2(bf16 a, bf16 b) {
    return ((unsigned)__bfloat16_as_ushort(b) << 16) | __bfloat16_as_ushort(a);
}
__device__ __forceinline__ void mma16816(float* d, const unsigned* a, const unsigned* b)
{
    asm volatile(
        "mma.sync.aligned.m16n8k16.row.col.f32.bf16.bf16.f32 "
        "{%0,%1,%2,%3}, {%4,%5,%6,%7}, {%8,%9}, {%0,%1,%2,%3};\n"
        : "+f"(d[0]), "+f"(d[1]), "+f"(d[2]), "+f"(d[3])
        : "r"(a[0]), "r"(a[1]), "r"(a[2]), "r"(a[3]), "r"(b[0]), "r"(b[1]));
}
__device__ __forceinline__ void ldm_x4(unsigned &r0, unsigned &r1, unsigned &r2, unsigned &r3,
                                       uint32_t addr)
{
    asm volatile("ldmatrix.sync.aligned.m8n8.x4.shared.b16 {%0,%1,%2,%3}, [%4];"
                 : "=r"(r0), "=r"(r1), "=r"(r2), "=r"(r3) : "r"(addr));
}
__device__ __forceinline__ void cpasync16(uint32_t dst, const void* src) {
    asm volatile("cp.async.cg.shared.global [%0], [%1], 16;" :: "r"(dst), "l"(src) : "memory");
}

// ---------------------------------------------------------------------------
// cp.async + ldmatrix NT GEMM core (round-12, proven).
// ---------------------------------------------------------------------------
#define DSMEM (2 * 32768)

template<bool GATHER, bool SPLITOUT>
__device__ __forceinline__ void gemm_core(
    const bf16* __restrict__ Ah_, const bf16* __restrict__ Al_, int lda,
    const bf16* __restrict__ Bh_, const bf16* __restrict__ Bl_, int ldb,
    int nch, int m0, int n0, float scale,
    float* __restrict__ Cf, bf16* __restrict__ Ch, bf16* __restrict__ Cl, int ldc)
{
    extern __shared__ char smemraw[];
    const uint32_t sbase = smem_u32(smemraw);
    const int tid = threadIdx.x;
    const int l = tid & 31, w = tid >> 5;
    const int wm = w >> 1, wn = w & 1;

    const int plane = (tid >> 2) & 1;
    const int k8    = tid & 3;
    const int r0    = tid >> 3;
    const int swu   = (tid & 7) ^ (r0 & 7);
    const bf16* Asrc = (plane ? Al_ : Ah_) + (size_t)(m0 + r0) * lda + k8 * 8;
    int brow = n0 + r0;
    if (GATHER) brow = g_rooms[n0 >> 8] * ROOM + ((n0 + r0) & 255);
    const bf16* Bsrc = (plane ? Bl_ : Bh_) + (size_t)brow * ldb + k8 * 8;
    const uint32_t dA0 = sbase + r0 * 128 + swu * 16;
    const uint32_t dB0 = dA0 + 16384;

    auto stage = [&](int kk, int buf) {
        const uint32_t boff = buf * 32768;
        const bf16* as = Asrc + kk;
        const bf16* bs = Bsrc + kk;
#pragma unroll
        for (int i = 0; i < 8; i++) {
            cpasync16(dA0 + boff + i * 2048, as + (size_t)i * 16 * lda);
            cpasync16(dB0 + boff + i * 2048, bs + (size_t)i * 16 * ldb);
        }
        asm volatile("cp.async.commit_group;" ::: "memory");
    };

    float acc[4][8][4];
#pragma unroll
    for (int i = 0; i < 4; i++)
#pragma unroll
        for (int j = 0; j < 8; j++)
#pragma unroll
            for (int r = 0; r < 4; r++) acc[i][j][r] = 0.f;

    stage(0, 0);
    stage(32, 1);

    for (int c = 0; c < nch; c++) {
        if (c + 1 < nch) asm volatile("cp.async.wait_group 1;" ::: "memory");
        else             asm volatile("cp.async.wait_group 0;" ::: "memory");
        __syncthreads();
        const uint32_t Ab = sbase + (c & 1) * 32768;
        const uint32_t Bb = Ab + 16384;
        const int mi = l >> 3;
        const int r8 = l & 7;

#pragma unroll
        for (int ks = 0; ks < 2; ks++) {
            unsigned bh[8][2], bl[8][2];
#pragma unroll
            for (int jp = 0; jp < 4; jp++) {
                int nl = wn * 64 + jp * 16 + (mi >> 1) * 8 + r8;
                int uh = (    ks * 2 + (mi & 1)) ^ (nl & 7);
                int ul = (4 + ks * 2 + (mi & 1)) ^ (nl & 7);
                ldm_x4(bh[2*jp][0], bh[2*jp][1], bh[2*jp+1][0], bh[2*jp+1][1],
                       Bb + nl * 128 + uh * 16);
                ldm_x4(bl[2*jp][0], bl[2*jp][1], bl[2*jp+1][0], bl[2*jp+1][1],
                       Bb + nl * 128 + ul * 16);
            }
#pragma unroll
            for (int i = 0; i < 4; i++) {
                int ml = wm * 64 + i * 16 + (mi & 1) * 8 + r8;
                int uh = (    ks * 2 + (mi >> 1)) ^ (ml & 7);
                int ul = (4 + ks * 2 + (mi >> 1)) ^ (ml & 7);
                unsigned ah[4], al[4];
                ldm_x4(ah[0], ah[1], ah[2], ah[3], Ab + ml * 128 + uh * 16);
                ldm_x4(al[0], al[1], al[2], al[3], Ab + ml * 128 + ul * 16);
#pragma unroll
                for (int j = 0; j < 8; j++) {
                    mma16816(acc[i][j], ah, bh[j]);
                    mma16816(acc[i][j], ah, bl[j]);
                    mma16816(acc[i][j], al, bh[j]);
                }
            }
        }
        __syncthreads();
        if (c + 2 < nch) stage((c + 2) * 32, c & 1);
    }

    const int g = l >> 2, t = l & 3;
#pragma unroll
    for (int i = 0; i < 4; i++) {
        size_t row = m0 + wm * 64 + i * 16 + g;
#pragma unroll
        for (int j = 0; j < 8; j++) {
            size_t col = n0 + wn * 64 + j * 8 + t * 2;
            if (!SPLITOUT) {
                *(float2*)&Cf[row * ldc + col] =
                    make_float2(acc[i][j][0] * scale, acc[i][j][1] * scale);
                *(float2*)&Cf[(row + 8) * ldc + col] =
                    make_float2(acc[i][j][2] * scale, acc[i][j][3] * scale);
            } else {
                bf16 h0, l0, h1, l1;
                split1(acc[i][j][0] * scale, h0, l0);
                split1(acc[i][j][1] * scale, h1, l1);
                *(unsigned*)&Ch[row * ldc + col] = pack2(h0, h1);
                *(unsigned*)&Cl[row * ldc + col] = pack2(l0, l1);
                split1(acc[i][j][2] * scale, h0, l0);
                split1(acc[i][j][3] * scale, h1, l1);
                *(unsigned*)&Ch[(row + 8) * ldc + col] = pack2(h0, h1);
                *(unsigned*)&Cl[(row + 8) * ldc + col] = pack2(l0, l1);
            }
        }
    }
}

// ---------------------------------------------------------------------------
// GEMM wrapper kernels
// ---------------------------------------------------------------------------
__global__ __launch_bounds__(128, 2) void k_qproj() {
    gemm_core<true, true>(g_Hh, g_Hl, H, g_QBh, g_QBl, H, 64,
                          blockIdx.y * 128, blockIdx.x * 128, 1.f,
                          nullptr, g_Qh, g_Ql, H);
}
__global__ __launch_bounds__(128, 2) void k_kproj() {
    gemm_core<false, true>(g_Hh, g_Hl, H, g_KBh, g_KBl, H, 64,
                           blockIdx.y * 128, blockIdx.x * 128, 1.f,
                           nullptr, g_Kh, g_Kl, ROOM);
}
__global__ __launch_bounds__(128, 2) void k_vprojT() {
    gemm_core<false, true>(g_VBh, g_VBl, H, g_Hh, g_Hl, H, 64,
                           blockIdx.y * 128, blockIdx.x * 128, 1.f,
                           nullptr, g_Vth, g_Vtl, S);
}
__global__ __launch_bounds__(128, 2) void k_scores(float* __restrict__ W) {
    if (blockIdx.x > blockIdx.y) return;   // strictly above diagonal
    const int h = blockIdx.z;
    gemm_core<false, false>(g_Qh + h * HD, g_Ql + h * HD, H,
                            g_Kh + (h & 1) * HD, g_Kl + (h & 1) * HD, ROOM,
                            4, blockIdx.y * 128, blockIdx.x * 128, SCALE,
                            W + (size_t)h * S * S, nullptr, nullptr, S);
}
__global__ __launch_bounds__(128, 2) void k_oproj(float* __restrict__ out) {
    gemm_core<false, false>(g_Ah, g_Al, H, g_OBth, g_OBtl, H, 64,
                            blockIdx.y * 128, blockIdx.x * 128, 1.f,
                            out, nullptr, nullptr, H);
}

// ---------------------------------------------------------------------------
// FUSED softmax + AV per (q-block by, head h). 128 threads.
// Pass 1: online per-row max/sum over raw scores (coalesced, per-thread
//   partials for 8 rows, smem combine). Zero-fills the upper W region.
// Pass 2 (per 32-col chunk): re-read raw, normalize, write final fp32 W,
//   split to bf16 planes directly into MMA A-staging smem, MMA against
//   double-buffered Vt planes. Epilogue: attn-out planes.
// Dyn smem: A-stage 16KB + B 2x16KB = 49152.
// ---------------------------------------------------------------------------
#define DSMEM2 (16384 + 2 * 16384)

__global__ __launch_bounds__(128, 2) void k_smav(float* __restrict__ W)
{
    extern __shared__ char smemraw[];
    __shared__ float2 prt[128][8];        // phase-A partials [thread][row-slot]
    __shared__ float  sm_m[128], sm_inv[128];
    const uint32_t sbase = smem_u32(smemraw);
    const int by = blockIdx.x, h = blockIdx.y;
    const int tid = threadIdx.x;
    const int l = tid & 31, w = tid >> 5;
    const int wm = w >> 1, wn = w & 1;
    const int q0 = by * 128;
    float* Wh = W + (size_t)h * S * S;
    const int nt = by + 1;
    const int Lt = nt * 128;
    const int nch = nt * 4;

    // ---- zero-fill W rows [q0, q0+128), cols [Lt, S) ----
    {
        int zw = (S - Lt) / 4;
        float4 z = make_float4(0.f, 0.f, 0.f, 0.f);
        for (int p = tid; p < 128 * zw; p += 128) {
            int r = p / zw, cc = p - r * zw;
            ((float4*)(Wh + (size_t)(q0 + r) * S + Lt))[cc] = z;
        }
    }

    // ---- phase A: online max/sum, coalesced; thread handles rows (tid>>3)+16i ----
    float am[8], as[8];
#pragma unroll
    for (int i = 0; i < 8; i++) { am[i] = -3.4e38f; as[i] = 0.f; }
    const int rbase = tid >> 3;
    const int c4 = tid & 7;
    for (int c = 0; c < nch; c++) {
#pragma unroll
        for (int i = 0; i < 8; i++) {
            int rr = rbase + 16 * i;
            int k0 = c * 32 + c4 * 4;
            int Lr = q0 + rr + 1;
            if (k0 >= Lr) continue;
            float4 x = *(const float4*)(Wh + (size_t)(q0 + rr) * S + k0);
            float x0 =                x.x;
            float x1 = (k0 + 1 < Lr) ? x.y : -3.4e38f;
            float x2 = (k0 + 2 < Lr) ? x.z : -3.4e38f;
            float x3 = (k0 + 3 < Lr) ? x.w : -3.4e38f;
            float mx = fmaxf(fmaxf(x0, x1), fmaxf(x2, x3));
            float nm = fmaxf(am[i], mx);
            as[i] = as[i] * __expf(am[i] - nm)
                  + __expf(x0 - nm) + __expf(x1 - nm)
                  + __expf(x2 - nm) + __expf(x3 - nm);
            am[i] = nm;
        }
    }
#pragma unroll
    for (int i = 0; i < 8; i++) prt[tid][i] = make_float2(am[i], as[i]);
    __syncthreads();
    // combine: thread r owns row r; partials at prt[(r&15)*8 + j][r>>4]
    {
        int g8 = (tid & 15) * 8, slot = tid >> 4;
        float m = -3.4e38f;
#pragma unroll
        for (int j = 0; j < 8; j++) m = fmaxf(m, prt[g8 + j][slot].x);
        float s = 0.f;
#pragma unroll
        for (int j = 0; j < 8; j++) {
            float2 P = prt[g8 + j][slot];
            s += P.y * __expf(P.x - m);
        }
        sm_m[tid] = m;
        sm_inv[tid] = 1.0f / s;
    }
    __syncthreads();

    // ---- phase B: normalize + write W + stage A planes + MMA ----
    // B (Vt planes) staging, gemm_core mapping
    const int plane = (tid >> 2) & 1;
    const int k8 = tid & 3;
    const int r0 = tid >> 3;
    const int swu = (tid & 7) ^ (r0 & 7);
    const bf16* Bsrc = (plane ? g_Vtl : g_Vth)
                     + (size_t)((h & 1) * 128 + r0) * S + k8 * 8;
    const uint32_t dB0 = sbase + 16384 + r0 * 128 + swu * 16;
    auto stageB = [&](int c, int buf) {
        const uint32_t boff = buf * 16384;
        const bf16* bs = Bsrc + c * 32;
#pragma unroll
        for (int i = 0; i < 8; i++)
            cpasync16(dB0 + boff + i * 2048, bs + (size_t)i * 16 * S);
        asm volatile("cp.async.commit_group;" ::: "memory");
    };

    float acc[4][8][4];
#pragma unroll
    for (int i = 0; i < 4; i++)
#pragma unroll
        for (int j = 0; j < 8; j++)
#pragma unroll
            for (int r = 0; r < 4; r++) acc[i][j][r] = 0.f;

    stageB(0, 0);
    stageB(1, 1);

    const int uA = c4 >> 1, subA = (c4 & 1) * 8;
    for (int c = 0; c < nch; c++) {
        // normalize chunk + write fp32 W + stage A planes
#pragma unroll
        for (int i = 0; i < 8; i++) {
            int rr = rbase + 16 * i;
            int k0 = c * 32 + c4 * 4;
            int Lr = q0 + rr + 1;
            float mr = sm_m[rr], ir = sm_inv[rr];
            float4 x = *(const float4*)(Wh + (size_t)(q0 + rr) * S + k0);
            float w0 = (k0     < Lr) ? __expf(x.x - mr) * ir : 0.f;
            float w1 = (k0 + 1 < Lr) ? __expf(x.y - mr) * ir : 0.f;
            float w2 = (k0 + 2 < Lr) ? __expf(x.z - mr) * ir : 0.f;
            float w3 = (k0 + 3 < Lr) ? __expf(x.w - mr) * ir : 0.f;
            *(float4*)(Wh + (size_t)(q0 + rr) * S + k0) = make_float4(w0, w1, w2, w3);
            bf16 h0, l0, h1, l1, h2, l2, h3, l3;
            split1(w0, h0, l0); split1(w1, h1, l1);
            split1(w2, h2, l2); split1(w3, h3, l3);
            int uh = uA ^ (rr & 7), ul = (uA + 4) ^ (rr & 7);
            *(uint2*)(smemraw + rr * 128 + uh * 16 + subA) =
                make_uint2(pack2(h0, h1), pack2(h2, h3));
            *(uint2*)(smemraw + rr * 128 + ul * 16 + subA) =
                make_uint2(pack2(l0, l1), pack2(l2, l3));
        }
        if (c + 1 < nch) asm volatile("cp.async.wait_group 1;" ::: "memory");
        else             asm volatile("cp.async.wait_group 0;" ::: "memory");
        __syncthreads();

        const uint32_t Ab = sbase;
        const uint32_t Bb = sbase + 16384 + (c & 1) * 16384;
        const int mi = l >> 3;
        const int r8 = l & 7;
#pragma unroll
        for (int ks = 0; ks < 2; ks++) {
            unsigned bh[8][2], bl[8][2];
#pragma unroll
            for (int jp = 0; jp < 4; jp++) {
                int nl = wn * 64 + jp * 16 + (mi >> 1) * 8 + r8;
                int uh = (    ks * 2 + (mi & 1)) ^ (nl & 7);
                int ul = (4 + ks * 2 + (mi & 1)) ^ (nl & 7);
                ldm_x4(bh[2*jp][0], bh[2*jp][1], bh[2*jp+1][0], bh[2*jp+1][1],
                       Bb + nl * 128 + uh * 16);
                ldm_x4(bl[2*jp][0], bl[2*jp][1], bl[2*jp+1][0], bl[2*jp+1][1],
                       Bb + nl * 128 + ul * 16);
            }
#pragma unroll
            for (int i = 0; i < 4; i++) {
                int ml = wm * 64 + i * 16 + (mi & 1) * 8 + r8;
                int uh = (    ks * 2 + (mi >> 1)) ^ (ml & 7);
                int ul = (4 + ks * 2 + (mi >> 1)) ^ (ml & 7);
                unsigned ah[4], al[4];
                ldm_x4(ah[0], ah[1], ah[2], ah[3], Ab + ml * 128 + uh * 16);
                ldm_x4(al[0], al[1], al[2], al[3], Ab + ml * 128 + ul * 16);
#pragma unroll
                for (int j = 0; j < 8; j++) {
                    mma16816(acc[i][j], ah, bh[j]);
                    mma16816(acc[i][j], ah, bl[j]);
                    mma16816(acc[i][j], al, bh[j]);
                }
            }
        }
        __syncthreads();
        if (c + 2 < nch) stageB(c + 2, c & 1);
    }

    // ---- epilogue: attn_out planes ----
    const int g = l >> 2, t = l & 3;
#pragma unroll
    for (int i = 0; i < 4; i++) {
        size_t row = q0 + wm * 64 + i * 16 + g;
#pragma unroll
        for (int j = 0; j < 8; j++) {
            size_t col = (size_t)h * HD + wn * 64 + j * 8 + t * 2;
            bf16 h0, l0, h1, l1;
            split1(acc[i][j][0], h0, l0);
            split1(acc[i][j][1], h1, l1);
            *(unsigned*)&g_Ah[row * H + col] = pack2(h0, h1);
            *(unsigned*)&g_Al[row * H + col] = pack2(l0, l1);
            split1(acc[i][j][2], h0, l0);
            split1(acc[i][j][3], h1, l1);
            *(unsigned*)&g_Ah[(row + 8) * H + col] = pack2(h0, h1);
            *(unsigned*)&g_Al[(row + 8) * H + col] = pack2(l0, l1);
        }
    }
}

// ---------------------------------------------------------------------------
// Pre-convert kernels
// ---------------------------------------------------------------------------
__global__ void normalize_rooms_kernel(const int* __restrict__ w) {
    bool is64 = (w[1] == 0) && (w[3] == 0) && (w[5] == 0) && (w[7] == 0);
    for (int i = 0; i < 8; i++)
        g_rooms[i] = is64 ? w[2 * i] : w[i];
}

__global__ __launch_bounds__(256) void conv_sel(const float* __restrict__ src,
                                                int which, int n4) {
    int i = blockIdx.x * 256 + threadIdx.x;
    if (i >= n4) return;
    bf16 *dh, *dl;
    if (which == 0)      { dh = g_Hh;  dl = g_Hl;  }
    else if (which == 1) { dh = g_QBh; dl = g_QBl; }
    else if (which == 2) { dh = g_KBh; dl = g_KBl; }
    else                 { dh = g_VBh; dl = g_VBl; }
    float4 v = ((const float4*)src)[i];
    bf16 h0, l0, h1, l1, h2, l2, h3, l3;
    split1(v.x, h0, l0); split1(v.y, h1, l1); split1(v.z, h2, l2); split1(v.w, h3, l3);
    ((uint2*)dh)[i] = make_uint2(pack2(h0, h1), pack2(h2, h3));
    ((uint2*)dl)[i] = make_uint2(pack2(l0, l1), pack2(l2, l3));
}

__global__ void conv_obt(const float* __restrict__ ob) {
    __shared__ float s[32][33];
    int t0 = blockIdx.y * 32, n0v = blockIdx.x * 32;
    int tx = threadIdx.x, ty = threadIdx.y;   // (32, 8)
#pragma unroll
    for (int i = 0; i < 4; i++) {
        int r = ty + i * 8;
        int sr = g_rooms[(t0 + r) >> 8] * ROOM + ((t0 + r) & 255);
        s[r][tx] = ob[(size_t)sr * H + n0v + tx];
    }
    __syncthreads();
#pragma unroll
    for (int i = 0; i < 4; i++) {
        int r = ty + i * 8;
        float v = s[tx][r];
        bf16 h, l;
        split1(v, h, l);
        g_OBth[(size_t)(n0v + r) * H + t0 + tx] = h;
        g_OBtl[(size_t)(n0v + r) * H + t0 + tx] = l;
    }
}

// ---------------------------------------------------------------------------
// Launch
// ---------------------------------------------------------------------------
extern "C" void kernel_launch(void* const* d_in, const int* in_sizes, int n_in,
                              void* d_out, int out_size)
{
    const float* hidden = (const float*)d_in[0];
    const float* qb     = (const float*)d_in[1];
    const float* kb     = (const float*)d_in[2];
    const float* vb     = (const float*)d_in[3];
    const float* ob     = (const float*)d_in[4];
    const int*   rooms_raw = (const int*)d_in[5];

    float* out   = (float*)d_out;
    float* o_out = out;                      // [S, H]
    float* W     = out + (size_t)S * H;      // [NH, S, S]

    (void)in_sizes; (void)n_in; (void)out_size;

    cudaFuncSetAttribute(k_qproj,  cudaFuncAttributeMaxDynamicSharedMemorySize, DSMEM);
    cudaFuncSetAttribute(k_kproj,  cudaFuncAttributeMaxDynamicSharedMemorySize, DSMEM);
    cudaFuncSetAttribute(k_vprojT, cudaFuncAttributeMaxDynamicSharedMemorySize, DSMEM);
    cudaFuncSetAttribute(k_scores, cudaFuncAttributeMaxDynamicSharedMemorySize, DSMEM);
    cudaFuncSetAttribute(k_smav,   cudaFuncAttributeMaxDynamicSharedMemorySize, DSMEM2);
    cudaFuncSetAttribute(k_oproj,  cudaFuncAttributeMaxDynamicSharedMemorySize, DSMEM);

    // 0) canonicalize rooms + pre-split operands to bf16 hi/lo planes
    normalize_rooms_kernel<<<1, 1>>>(rooms_raw);
    conv_sel<<<(S * H / 4) / 256, 256>>>(hidden, 0, S * H / 4);
    conv_sel<<<(H * H / 4) / 256, 256>>>(qb, 1, H * H / 4);
    conv_sel<<<(ROOM * H / 4) / 256, 256>>>(kb, 2, ROOM * H / 4);
    conv_sel<<<(ROOM * H / 4) / 256, 256>>>(vb, 3, ROOM * H / 4);
    conv_obt<<<dim3(H / 32, H / 32), dim3(32, 8)>>>(ob);

    // 1) projections
    k_qproj <<<dim3(16, 16), 128, DSMEM>>>();
    k_kproj <<<dim3(2, 16),  128, DSMEM>>>();
    k_vprojT<<<dim3(16, 2),  128, DSMEM>>>();

    // 2) scores (raw, scaled, lower-triangular tiles)
    k_scores<<<dim3(16, 16, NH), 128, DSMEM>>>(W);

    // 3) fused softmax + AV (writes final W + attn-out planes)
    k_smav<<<dim3(16, 16), 128, DSMEM2>>>(W);

    // 4) O projection
    k_oproj<<<dim3(16, 16), 128, DSMEM>>>(o_out);
}

// round 14
// speedup vs baseline: 1.9473x; 1.9473x over previous
#include <cuda_runtime.h>
#include <cuda_bf16.h>
#include <cstdint>
#include <math.h>

#define S   2048
#define H   2048
#define ROOM 256
#define NH  16
#define HD  128
#define SCALE 0.08838834764831845f  // 1/sqrt(128)

typedef __nv_bfloat16 bf16;

// ---------------- device globals (allocation-free scratch) ----------------
__device__ __align__(16) bf16 g_Hh [(size_t)S*H],    g_Hl [(size_t)S*H];     // hidden planes
__device__ __align__(16) bf16 g_QBh[(size_t)H*H],    g_QBl[(size_t)H*H];     // q_block planes
__device__ __align__(16) bf16 g_KBh[(size_t)ROOM*H], g_KBl[(size_t)ROOM*H];  // k_block planes
__device__ __align__(16) bf16 g_VBh[(size_t)ROOM*H], g_VBl[(size_t)ROOM*H];  // v_block planes
__device__ __align__(16) bf16 g_OBth[(size_t)H*H],   g_OBtl[(size_t)H*H];    // o_active^T [n][t]
__device__ __align__(16) bf16 g_Qh [(size_t)S*H],    g_Ql [(size_t)S*H];     // Q projection planes
__device__ __align__(16) bf16 g_Kh [(size_t)S*ROOM], g_Kl [(size_t)S*ROOM];  // k_one planes
__device__ __align__(16) bf16 g_Vth[(size_t)ROOM*S], g_Vtl[(size_t)ROOM*S];  // v_one^T [d][s]
__device__ __align__(16) bf16 g_Wh [(size_t)NH*S*S], g_Wl [(size_t)NH*S*S];  // softmaxed W planes
__device__ __align__(16) bf16 g_Ah [(size_t)S*H],    g_Al [(size_t)S*H];     // attn_out planes
__device__ int g_rooms[8];

// ---------------- helpers ----------------
__device__ __forceinline__ uint32_t smem_u32(const void* p) {
    uint32_t a;
    asm("{ .reg .u64 t; cvta.to.shared.u64 t, %1; cvt.u32.u64 %0, t; }" : "=r"(a) : "l"(p));
    return a;
}
__device__ __forceinline__ void split1(float x, bf16& h, bf16& l) {
    h = __float2bfloat16_rn(x);
    l = __float2bfloat16_rn(x - __bfloat162float(h));
}
__device__ __forceinline__ unsigned pack2(bf16 a, bf16 b) {
    return ((unsigned)__bfloat16_as_ushort(b) << 16) | __bfloat16_as_ushort(a);
}
__device__ __forceinline__ void mma16816(float* d, const unsigned* a, const unsigned* b)
{
    asm volatile(
        "mma.sync.aligned.m16n8k16.row.col.f32.bf16.bf16.f32 "
        "{%0,%1,%2,%3}, {%4,%5,%6,%7}, {%8,%9}, {%0,%1,%2,%3};\n"
        : "+f"(d[0]), "+f"(d[1]), "+f"(d[2]), "+f"(d[3])
        : "r"(a[0]), "r"(a[1]), "r"(a[2]), "r"(a[3]), "r"(b[0]), "r"(b[1]));
}
__device__ __forceinline__ void ldm_x4(unsigned &r0, unsigned &r1, unsigned &r2, unsigned &r3,
                                       uint32_t addr)
{
    asm volatile("ldmatrix.sync.aligned.m8n8.x4.shared.b16 {%0,%1,%2,%3}, [%4];"
                 : "=r"(r0), "=r"(r1), "=r"(r2), "=r"(r3) : "r"(addr));
}
__device__ __forceinline__ void cpasync16(uint32_t dst, const void* src) {
    asm volatile("cp.async.cg.shared.global [%0], [%1], 16;" :: "r"(dst), "l"(src) : "memory");
}

// ---------------------------------------------------------------------------
// cp.async + ldmatrix NT GEMM core (round-12, proven).
// C[128,128] = A[M,K] @ B[N,K]^T, 3-term split (hh+hl+lh), fp32 accum.
// 128 threads, 4 warps (2x2 of 64x64), BK=32, double-buffered. Smem 64KB.
// ---------------------------------------------------------------------------
#define DSMEM (2 * 32768)

template<bool GATHER, bool SPLITOUT>
__device__ __forceinline__ void gemm_core(
    const bf16* __restrict__ Ah_, const bf16* __restrict__ Al_, int lda,
    const bf16* __restrict__ Bh_, const bf16* __restrict__ Bl_, int ldb,
    int nch, int m0, int n0, float scale,
    float* __restrict__ Cf, bf16* __restrict__ Ch, bf16* __restrict__ Cl, int ldc)
{
    extern __shared__ char smemraw[];
    const uint32_t sbase = smem_u32(smemraw);
    const int tid = threadIdx.x;
    const int l = tid & 31, w = tid >> 5;
    const int wm = w >> 1, wn = w & 1;

    const int plane = (tid >> 2) & 1;
    const int k8    = tid & 3;
    const int r0    = tid >> 3;
    const int swu   = (tid & 7) ^ (r0 & 7);
    const bf16* Asrc = (plane ? Al_ : Ah_) + (size_t)(m0 + r0) * lda + k8 * 8;
    int brow = n0 + r0;
    if (GATHER) brow = g_rooms[n0 >> 8] * ROOM + ((n0 + r0) & 255);
    const bf16* Bsrc = (plane ? Bl_ : Bh_) + (size_t)brow * ldb + k8 * 8;
    const uint32_t dA0 = sbase + r0 * 128 + swu * 16;
    const uint32_t dB0 = dA0 + 16384;

    auto stage = [&](int kk, int buf) {
        const uint32_t boff = buf * 32768;
        const bf16* as = Asrc + kk;
        const bf16* bs = Bsrc + kk;
#pragma unroll
        for (int i = 0; i < 8; i++) {
            cpasync16(dA0 + boff + i * 2048, as + (size_t)i * 16 * lda);
            cpasync16(dB0 + boff + i * 2048, bs + (size_t)i * 16 * ldb);
        }
        asm volatile("cp.async.commit_group;" ::: "memory");
    };

    float acc[4][8][4];
#pragma unroll
    for (int i = 0; i < 4; i++)
#pragma unroll
        for (int j = 0; j < 8; j++)
#pragma unroll
            for (int r = 0; r < 4; r++) acc[i][j][r] = 0.f;

    stage(0, 0);
    stage(32, 1);

    for (int c = 0; c < nch; c++) {
        if (c + 1 < nch) asm volatile("cp.async.wait_group 1;" ::: "memory");
        else             asm volatile("cp.async.wait_group 0;" ::: "memory");
        __syncthreads();
        const uint32_t Ab = sbase + (c & 1) * 32768;
        const uint32_t Bb = Ab + 16384;
        const int mi = l >> 3;
        const int r8 = l & 7;

#pragma unroll
        for (int ks = 0; ks < 2; ks++) {
            unsigned bh[8][2], bl[8][2];
#pragma unroll
            for (int jp = 0; jp < 4; jp++) {
                int nl = wn * 64 + jp * 16 + (mi >> 1) * 8 + r8;
                int uh = (    ks * 2 + (mi & 1)) ^ (nl & 7);
                int ul = (4 + ks * 2 + (mi & 1)) ^ (nl & 7);
                ldm_x4(bh[2*jp][0], bh[2*jp][1], bh[2*jp+1][0], bh[2*jp+1][1],
                       Bb + nl * 128 + uh * 16);
                ldm_x4(bl[2*jp][0], bl[2*jp][1], bl[2*jp+1][0], bl[2*jp+1][1],
                       Bb + nl * 128 + ul * 16);
            }
#pragma unroll
            for (int i = 0; i < 4; i++) {
                int ml = wm * 64 + i * 16 + (mi & 1) * 8 + r8;
                int uh = (    ks * 2 + (mi >> 1)) ^ (ml & 7);
                int ul = (4 + ks * 2 + (mi >> 1)) ^ (ml & 7);
                unsigned ah[4], al[4];
                ldm_x4(ah[0], ah[1], ah[2], ah[3], Ab + ml * 128 + uh * 16);
                ldm_x4(al[0], al[1], al[2], al[3], Ab + ml * 128 + ul * 16);
#pragma unroll
                for (int j = 0; j < 8; j++) {
                    mma16816(acc[i][j], ah, bh[j]);
                    mma16816(acc[i][j], ah, bl[j]);
                    mma16816(acc[i][j], al, bh[j]);
                }
            }
        }
        __syncthreads();
        if (c + 2 < nch) stage((c + 2) * 32, c & 1);
    }

    const int g = l >> 2, t = l & 3;
#pragma unroll
    for (int i = 0; i < 4; i++) {
        size_t row = m0 + wm * 64 + i * 16 + g;
#pragma unroll
        for (int j = 0; j < 8; j++) {
            size_t col = n0 + wn * 64 + j * 8 + t * 2;
            if (!SPLITOUT) {
                *(float2*)&Cf[row * ldc + col] =
                    make_float2(acc[i][j][0] * scale, acc[i][j][1] * scale);
                *(float2*)&Cf[(row + 8) * ldc + col] =
                    make_float2(acc[i][j][2] * scale, acc[i][j][3] * scale);
            } else {
                bf16 h0, l0, h1, l1;
                split1(acc[i][j][0] * scale, h0, l0);
                split1(acc[i][j][1] * scale, h1, l1);
                *(unsigned*)&Ch[row * ldc + col] = pack2(h0, h1);
                *(unsigned*)&Cl[row * ldc + col] = pack2(l0, l1);
                split1(acc[i][j][2] * scale, h0, l0);
                split1(acc[i][j][3] * scale, h1, l1);
                *(unsigned*)&Ch[(row + 8) * ldc + col] = pack2(h0, h1);
                *(unsigned*)&Cl[(row + 8) * ldc + col] = pack2(l0, l1);
            }
        }
    }
}

// ---------------------------------------------------------------------------
// MERGED projection kernel: qproj (256 CTAs) + kproj (32) + vprojT (32)
// in one 320-CTA launch so the small GEMMs fill qproj's wave.
// ---------------------------------------------------------------------------
__global__ __launch_bounds__(128, 2) void k_proj3() {
    int idx = blockIdx.x;
    if (idx < 256) {
        // Q projection (gathered q_block rows)
        int bx = idx & 15, by = idx >> 4;
        gemm_core<true, true>(g_Hh, g_Hl, H, g_QBh, g_QBl, H, 64,
                              by * 128, bx * 128, 1.f,
                              nullptr, g_Qh, g_Ql, H);
    } else if (idx < 288) {
        // K projection
        int i = idx - 256;
        int bx = i & 1, by = i >> 1;
        gemm_core<false, true>(g_Hh, g_Hl, H, g_KBh, g_KBl, H, 64,
                               by * 128, bx * 128, 1.f,
                               nullptr, g_Kh, g_Kl, ROOM);
    } else {
        // Vt[d, s] = vb[d,:] . hidden[s,:]
        int i = idx - 288;
        int bx = i & 15, by = i >> 4;
        gemm_core<false, true>(g_VBh, g_VBl, H, g_Hh, g_Hl, H, 64,
                               by * 128, bx * 128, 1.f,
                               nullptr, g_Vth, g_Vtl, S);
    }
}

// scores: compacted lower-triangular grid (136 tiles per head)
__global__ __launch_bounds__(128, 2) void k_scores(float* __restrict__ W) {
    const int h = blockIdx.y;
    int t = blockIdx.x;                         // 0..135
    int by = (int)((sqrtf(8.f * t + 1.f) - 1.f) * 0.5f);
    // guard float rounding
    while ((by + 1) * (by + 2) / 2 <= t) by++;
    while (by * (by + 1) / 2 > t) by--;
    int bx = t - by * (by + 1) / 2;
    gemm_core<false, false>(g_Qh + h * HD, g_Ql + h * HD, H,
                            g_Kh + (h & 1) * HD, g_Kl + (h & 1) * HD, ROOM,
                            4, by * 128, bx * 128, SCALE,
                            W + (size_t)h * S * S, nullptr, nullptr, S);
}

// AV: A[q, h*128+d] = sum_k W[q,k] Vt[d,k]   (K causally limited)
__global__ __launch_bounds__(128, 2) void k_av() {
    const int h = blockIdx.z, by = blockIdx.y;
    gemm_core<false, true>(g_Wh + (size_t)h * S * S, g_Wl + (size_t)h * S * S, S,
                           g_Vth + (size_t)(h & 1) * 128 * S,
                           g_Vtl + (size_t)(h & 1) * 128 * S, S,
                           (by + 1) * 4, by * 128, 0, 1.f,
                           nullptr, g_Ah + h * HD, g_Al + h * HD, H);
}
__global__ __launch_bounds__(128, 2) void k_oproj(float* __restrict__ out) {
    gemm_core<false, false>(g_Ah, g_Al, H, g_OBth, g_OBtl, H, 64,
                            blockIdx.y * 128, blockIdx.x * 128, 1.f,
                            out, nullptr, nullptr, H);
}

// ---------------------------------------------------------------------------
// Pre-convert kernels
// ---------------------------------------------------------------------------
__global__ void normalize_rooms_kernel(const int* __restrict__ w) {
    bool is64 = (w[1] == 0) && (w[3] == 0) && (w[5] == 0) && (w[7] == 0);
    for (int i = 0; i < 8; i++)
        g_rooms[i] = is64 ? w[2 * i] : w[i];
}

// one launch for all 4 plane conversions; ranges decoded per-thread
#define N4_H   (S * H / 4)       // 1048576
#define N4_QB  (H * H / 4)       // 1048576
#define N4_KB  (ROOM * H / 4)    // 131072
#define N4_ALL (N4_H + N4_QB + 2 * N4_KB)

__global__ __launch_bounds__(256) void conv_all(
    const float* __restrict__ hidden, const float* __restrict__ qb,
    const float* __restrict__ kb, const float* __restrict__ vb)
{
    int i = blockIdx.x * 256 + threadIdx.x;
    if (i >= N4_ALL) return;
    const float* src;
    bf16 *dh, *dl;
    int o = i;
    if (o < N4_H)                 { src = hidden; dh = g_Hh;  dl = g_Hl;  }
    else if ((o -= N4_H) < N4_QB) { src = qb;     dh = g_QBh; dl = g_QBl; }
    else if ((o -= N4_QB) < N4_KB){ src = kb;     dh = g_KBh; dl = g_KBl; }
    else          { o -= N4_KB;     src = vb;     dh = g_VBh; dl = g_VBl; }
    float4 v = ((const float4*)src)[o];
    bf16 h0, l0, h1, l1, h2, l2, h3, l3;
    split1(v.x, h0, l0); split1(v.y, h1, l1); split1(v.z, h2, l2); split1(v.w, h3, l3);
    ((uint2*)dh)[o] = make_uint2(pack2(h0, h1), pack2(h2, h3));
    ((uint2*)dl)[o] = make_uint2(pack2(l0, l1), pack2(l2, l3));
}

// transpose + gather: OBt[n][t] = ob[rooms[t>>8]*256 + (t&255)][n]
__global__ void conv_obt(const float* __restrict__ ob) {
    __shared__ float s[32][33];
    int t0 = blockIdx.y * 32, n0v = blockIdx.x * 32;
    int tx = threadIdx.x, ty = threadIdx.y;   // (32, 8)
#pragma unroll
    for (int i = 0; i < 4; i++) {
        int r = ty + i * 8;
        int sr = g_rooms[(t0 + r) >> 8] * ROOM + ((t0 + r) & 255);
        s[r][tx] = ob[(size_t)sr * H + n0v + tx];
    }
    __syncthreads();
#pragma unroll
    for (int i = 0; i < 4; i++) {
        int r = ty + i * 8;
        float v = s[tx][r];
        bf16 h, l;
        split1(v, h, l);
        g_OBth[(size_t)(n0v + r) * H + t0 + tx] = h;
        g_OBtl[(size_t)(n0v + r) * H + t0 + tx] = l;
    }
}

// ---------------------------------------------------------------------------
// Softmax per (head, q-row): one read; writes fp32 W (full row) + bf16 hi/lo
// planes zero-filled to the q-block boundary (AV's K range reads exact zeros).
// ---------------------------------------------------------------------------
__global__ __launch_bounds__(256) void softmax_kernel(float* __restrict__ W) {
    const int q = blockIdx.x, h = blockIdx.y;
    float* row = W + ((size_t)h * S + q) * S;
    unsigned* rh = (unsigned*)(g_Wh + ((size_t)h * S + q) * S);
    unsigned* rl = (unsigned*)(g_Wl + ((size_t)h * S + q) * S);
    const int L = q + 1;
    const int Lpad = ((q >> 7) + 1) << 7;
    const int tid = threadIdx.x;
    __shared__ float sh[8];

    float2 v[4];
    float m = -3.4e38f;
#pragma unroll
    for (int i = 0; i < 4; i++) {
        int p = tid + i * 256;
        float2 x = ((const float2*)row)[p];
        int k0 = p * 2;
        v[i].x = (k0     < L) ? x.x : -3.4e38f;
        v[i].y = (k0 + 1 < L) ? x.y : -3.4e38f;
        m = fmaxf(m, fmaxf(v[i].x, v[i].y));
    }
#pragma unroll
    for (int o = 16; o > 0; o >>= 1) m = fmaxf(m, __shfl_xor_sync(0xffffffffu, m, o));
    if ((tid & 31) == 0) sh[tid >> 5] = m;
    __syncthreads();
    float mm = sh[0];
#pragma unroll
    for (int i = 1; i < 8; i++) mm = fmaxf(mm, sh[i]);
    __syncthreads();

    float ex[4], ey[4], ssum = 0.f;
#pragma unroll
    for (int i = 0; i < 4; i++) {
        int k0 = (tid + i * 256) * 2;
        ex[i] = (k0     < L) ? __expf(v[i].x - mm) : 0.f;
        ey[i] = (k0 + 1 < L) ? __expf(v[i].y - mm) : 0.f;
        ssum += ex[i] + ey[i];
    }
#pragma unroll
    for (int o = 16; o > 0; o >>= 1) ssum += __shfl_xor_sync(0xffffffffu, ssum, o);
    if ((tid & 31) == 0) sh[tid >> 5] = ssum;
    __syncthreads();
    float tot = 0.f;
#pragma unroll
    for (int i = 0; i < 8; i++) tot += sh[i];
    const float inv = 1.0f / tot;

#pragma unroll
    for (int i = 0; i < 4; i++) {
        int p = tid + i * 256;
        int k0 = p * 2;
        float wx = ex[i] * inv, wy = ey[i] * inv;
        ((float2*)row)[p] = make_float2(wx, wy);
        if (k0 < Lpad) {
            bf16 h0, l0, h1, l1;
            split1(wx, h0, l0); split1(wy, h1, l1);
            rh[p] = pack2(h0, h1);
            rl[p] = pack2(l0, l1);
        }
    }
}

// ---------------------------------------------------------------------------
// Launch
// ---------------------------------------------------------------------------
extern "C" void kernel_launch(void* const* d_in, const int* in_sizes, int n_in,
                              void* d_out, int out_size)
{
    const float* hidden = (const float*)d_in[0];
    const float* qb     = (const float*)d_in[1];
    const float* kb     = (const float*)d_in[2];
    const float* vb     = (const float*)d_in[3];
    const float* ob     = (const float*)d_in[4];
    const int*   rooms_raw = (const int*)d_in[5];

    float* out   = (float*)d_out;
    float* o_out = out;                      // [S, H]
    float* W     = out + (size_t)S * H;      // [NH, S, S]

    (void)in_sizes; (void)n_in; (void)out_size;

    cudaFuncSetAttribute(k_proj3,  cudaFuncAttributeMaxDynamicSharedMemorySize, DSMEM);
    cudaFuncSetAttribute(k_scores, cudaFuncAttributeMaxDynamicSharedMemorySize, DSMEM);
    cudaFuncSetAttribute(k_av,     cudaFuncAttributeMaxDynamicSharedMemorySize, DSMEM);
    cudaFuncSetAttribute(k_oproj,  cudaFuncAttributeMaxDynamicSharedMemorySize, DSMEM);

    // 0) canonicalize rooms + pre-split operands to bf16 hi/lo planes
    normalize_rooms_kernel<<<1, 1>>>(rooms_raw);
    conv_all<<<(N4_ALL + 255) / 256, 256>>>(hidden, qb, kb, vb);
    conv_obt<<<dim3(H / 32, H / 32), dim3(32, 8)>>>(ob);

    // 1) all three projections in one wave-filling launch
    k_proj3<<<320, 128, DSMEM>>>();

    // 2) scores (compacted lower-triangular grid)
    k_scores<<<dim3(136, NH), 128, DSMEM>>>(W);

    // 3) softmax (fp32 W + bf16 planes)
    softmax_kernel<<<dim3(S, NH), 256>>>(W);

    // 4) AV
    k_av<<<dim3(1, 16, NH), 128, DSMEM>>>();

    // 5) O projection
    k_oproj<<<dim3(16, 16), 128, DSMEM>>>(o_out);
}